// round 14
// baseline (speedup 1.0000x reference)
#include <cuda_runtime.h>
#include <math.h>
#include <stdint.h>

#define DIM   1024
#define NH    16
#define HD    64
#define B_    2
#define S_    2048
#define MROWS (B_ * S_)   // 4096

// Scratch (allocation-free rule: __device__ globals)
__device__ float g_Q[B_ * NH * S_ * HD];   // [B,H,S,hd]
__device__ float g_K[B_ * NH * S_ * HD];
__device__ float g_V[B_ * NH * S_ * HD];
__device__ float g_C[MROWS * DIM];         // attention context (tf32-rounded)
__device__ float g_Xr[MROWS * DIM];        // x, tf32-RNA-rounded
__device__ float g_Wr[4 * DIM * DIM];      // Wq|Wk|Wv|Wo, tf32-RNA-rounded

// ---------------------------------------------------------------------------
// TF32 / async helpers
// ---------------------------------------------------------------------------
__device__ __forceinline__ uint32_t f2tf(float f) {
    uint32_t r;
    asm("cvt.rna.tf32.f32 %0, %1;" : "=r"(r) : "f"(f));
    return r;
}
__device__ __forceinline__ float tfr(float f) { return __uint_as_float(f2tf(f)); }

__device__ __forceinline__ void mma_tf32(float* d, const uint32_t* a, const uint32_t* b) {
    asm volatile(
        "mma.sync.aligned.m16n8k8.row.col.f32.tf32.tf32.f32 "
        "{%0,%1,%2,%3}, {%4,%5,%6,%7}, {%8,%9}, {%0,%1,%2,%3};"
        : "+f"(d[0]), "+f"(d[1]), "+f"(d[2]), "+f"(d[3])
        : "r"(a[0]), "r"(a[1]), "r"(a[2]), "r"(a[3]),
          "r"(b[0]), "r"(b[1]));
}

__device__ __forceinline__ void cp_async16(uint32_t smem_byte_addr, const void* gptr) {
    asm volatile("cp.async.cg.shared.global [%0], [%1], 16;"
                 :: "r"(smem_byte_addr), "l"(gptr));
}
__device__ __forceinline__ void cp_commit() { asm volatile("cp.async.commit_group;"); }
__device__ __forceinline__ void cp_wait0()  { asm volatile("cp.async.wait_group 0;"); }

// ---------------------------------------------------------------------------
// Pre-round x and the four weight matrices to tf32-RNA.
// ---------------------------------------------------------------------------
#define X4 (MROWS * DIM / 4)   // 1048576
#define W4 (DIM * DIM / 4)     // 262144

__global__ void round_tf32_kernel(
    const float* __restrict__ x,
    const float* __restrict__ wq, const float* __restrict__ wk,
    const float* __restrict__ wv, const float* __restrict__ wo,
    float* __restrict__ xr, float* __restrict__ wr)
{
    const int gid = blockIdx.x * blockDim.x + threadIdx.x;
    const float4* src;
    float4* dst;
    int idx;
    if (gid < X4) {
        src = (const float4*)x;  dst = (float4*)xr;  idx = gid;
    } else {
        const int t = gid - X4;
        const int w = t >> 18;          // / W4
        idx = t & (W4 - 1);
        src = (const float4*)(w == 0 ? wq : w == 1 ? wk : w == 2 ? wv : wo);
        dst = (float4*)(wr + (size_t)w * DIM * DIM);
    }
    float4 v = src[idx];
    v.x = tfr(v.x); v.y = tfr(v.y); v.z = tfr(v.z); v.w = tfr(v.w);
    dst[idx] = v;
}

// ---------------------------------------------------------------------------
// TF32 GEMM v2: 128 threads, 4 warps, warp tile 64x64 (2x2 warp grid).
// Block 128x128x16, cp.async double-buffered, 1 barrier/tile.
// QKV=1: fused N=3072 (per-CTA weight select), scatter to [B,H,S,hd], tfr out.
// QKV=0: N=1024, row-major out + bias.
// ---------------------------------------------------------------------------
#define LDA 20
#define LDB 136

template<int QKV>
__global__ __launch_bounds__(128, 2) void gemm_tf32_kernel(
    const float* __restrict__ A, const float* __restrict__ Wall,
    const float* __restrict__ b0, const float* __restrict__ b1,
    const float* __restrict__ b2,
    float* __restrict__ O0, float* __restrict__ O1, float* __restrict__ O2)
{
    __shared__ uint32_t As[2][128 * LDA];
    __shared__ uint32_t Bs[2][16 * LDB];

    const int tid  = threadIdx.x;
    const int lane = tid & 31;
    const int warp = tid >> 5;
    const int bm  = blockIdx.y * 128;
    const int bnG = blockIdx.x * 128;
    const int wsel = bnG >> 10;
    const int bn   = bnG & 1023;
    const int wm = (warp & 1) << 6;      // 0 / 64
    const int wn = (warp >> 1) << 6;     // 0 / 64

    const float* W    = Wall + (size_t)wsel * DIM * DIM;
    const float* bias = QKV ? (wsel == 0 ? b0 : (wsel == 1 ? b1 : b2)) : b0;
    float* Osel = QKV ? (wsel == 0 ? O0 : (wsel == 1 ? O1 : O2)) : O0;

    const int ar  = tid >> 2;            // 0..31 (+32,+64,+96)
    const int akc = (tid & 3) << 2;
    const int bk  = tid >> 5;            // 0..3 (+4,+8,+12)
    const int bnc = (tid & 31) << 2;

    const float* Ap = A + (size_t)(bm + ar) * DIM + akc;
    const float* Bp = W + (size_t)bk * DIM + bn + bnc;

    const uint32_t as_b = (uint32_t)__cvta_generic_to_shared(As);
    const uint32_t bs_b = (uint32_t)__cvta_generic_to_shared(Bs);

    auto issue = [&](int kt, int bf) {
        const float* a = Ap + kt * 16;
#pragma unroll
        for (int rr = 0; rr < 4; rr++)
            cp_async16(as_b + (bf * 128 * LDA + (ar + rr * 32) * LDA + akc) * 4,
                       a + (size_t)(rr * 32) * DIM);
        const float* b = Bp + (size_t)kt * 16 * DIM;
#pragma unroll
        for (int rr = 0; rr < 4; rr++)
            cp_async16(bs_b + (bf * 16 * LDB + (bk + rr * 4) * LDB + bnc) * 4,
                       b + (size_t)(rr * 4) * DIM);
        cp_commit();
    };

    float acc[32][4];
#pragma unroll
    for (int i = 0; i < 32; i++)
#pragma unroll
        for (int j = 0; j < 4; j++) acc[i][j] = 0.0f;

    issue(0, 0);

    const int NT = DIM / 16;
#pragma unroll 1
    for (int kt = 0; kt < NT; kt++) {
        cp_wait0();
        __syncthreads();
        if (kt + 1 < NT) issue(kt + 1, (kt + 1) & 1);
        const int cur = kt & 1;

#pragma unroll
        for (int ks = 0; ks < 2; ks++) {
            uint32_t af[4][4], bf[8][2];
#pragma unroll
            for (int mi = 0; mi < 4; mi++) {
                const int r = wm + mi * 16 + (lane >> 2);
                const int c = ks * 8 + (lane & 3);
                af[mi][0] = As[cur][r * LDA + c];
                af[mi][1] = As[cur][(r + 8) * LDA + c];
                af[mi][2] = As[cur][r * LDA + c + 4];
                af[mi][3] = As[cur][(r + 8) * LDA + c + 4];
            }
#pragma unroll
            for (int ni = 0; ni < 8; ni++) {
                const int n = wn + ni * 8 + (lane >> 2);
                const int k = ks * 8 + (lane & 3);
                bf[ni][0] = Bs[cur][k * LDB + n];
                bf[ni][1] = Bs[cur][(k + 4) * LDB + n];
            }
#pragma unroll
            for (int mi = 0; mi < 4; mi++)
#pragma unroll
                for (int ni = 0; ni < 8; ni++)
                    mma_tf32(acc[mi * 8 + ni], af[mi], bf[ni]);
        }
    }

#pragma unroll
    for (int mi = 0; mi < 4; mi++) {
        const int r0 = bm + wm + mi * 16 + (lane >> 2);
        const int r1 = r0 + 8;
#pragma unroll
        for (int ni = 0; ni < 8; ni++) {
            const int c0 = bn + wn + ni * 8 + ((lane & 3) << 1);
            const float* a = acc[mi * 8 + ni];
            const float bi0 = bias[c0], bi1 = bias[c0 + 1];
            if (QKV == 0) {
                *(float2*)&Osel[(size_t)r0 * DIM + c0] = make_float2(a[0] + bi0, a[1] + bi1);
                *(float2*)&Osel[(size_t)r1 * DIM + c0] = make_float2(a[2] + bi0, a[3] + bi1);
            } else {
                const int h = c0 >> 6, d = c0 & 63;
                const int b0r = r0 >> 11, s0 = r0 & (S_ - 1);
                const int b1r = r1 >> 11, s1 = r1 & (S_ - 1);
                *(float2*)&Osel[(((size_t)(b0r * NH + h)) * S_ + s0) * HD + d] =
                    make_float2(tfr(a[0] + bi0), tfr(a[1] + bi1));
                *(float2*)&Osel[(((size_t)(b1r * NH + h)) * S_ + s1) * HD + d] =
                    make_float2(tfr(a[2] + bi0), tfr(a[3] + bi1));
            }
        }
    }
}

// ---------------------------------------------------------------------------
// RoPE (in-place on Q and K), tf32-RNA-rounded outputs.
// ---------------------------------------------------------------------------
__global__ void rope_kernel(float* __restrict__ Q, float* __restrict__ K,
                            const float* __restrict__ theta)
{
    const int gid  = blockIdx.x * blockDim.x + threadIdx.x;
    const int warp = gid >> 5;
    const int lane = gid & 31;
    const int s = warp & (S_ - 1);

    const float th = theta[lane];
    float sn, cs;
    sincosf((float)s * th, &sn, &cs);

    float* q = Q + (size_t)warp * HD;
    float x1 = q[2 * lane], x2 = q[2 * lane + 1];
    __syncwarp();
    q[lane]      = tfr(x1 * cs - x2 * sn);
    q[lane + 32] = tfr(x1 * sn + x2 * cs);

    float* k = K + (size_t)warp * HD;
    float y1 = k[2 * lane], y2 = k[2 * lane + 1];
    __syncwarp();
    k[lane]      = tfr(y1 * cs - y2 * sn);
    k[lane + 32] = tfr(y1 * sn + y2 * cs);
}

// ---------------------------------------------------------------------------
// TF32 flash attention v6: as v5 (4 warps, 32 q-rows/warp, register Q,
// cp.async double buffer, diag skip) + QK^T loop interchange on full tiles:
// ks-outer / nt-inner fully unrolled -> 16 independent MMA chains (was 2),
// removing the dependent-MMA stall that capped tensor pipe at ~38%.
// Per-accumulator k-order unchanged (ks ascending) -> bit-identical output.
// ---------------------------------------------------------------------------
#define KLD 68
#define VLD 72
#define PLD 68
#define KBUF (64 * KLD)
#define VBUF (64 * VLD)
#define FLASH_SMEM_WORDS (2*KBUF + 2*VBUF + 128*PLD)   // 106.5 KB

__global__ __launch_bounds__(128, 2) void flash_tf32_kernel(
    const float* __restrict__ Q, const float* __restrict__ K,
    const float* __restrict__ V, float* __restrict__ ctx)
{
    extern __shared__ uint32_t sm[];
    uint32_t* Ks = sm;
    uint32_t* Vs = Ks + 2 * KBUF;
    uint32_t* Ps = Vs + 2 * VBUF;

    const int bid  = blockIdx.x;
    const int qb   = 15 - (bid >> 5);
    const int bh   = bid & 31;
    const int tid  = threadIdx.x;
    const int lane = tid & 31;
    const int warp = tid >> 5;
    const int g = lane >> 2;
    const int c = lane & 3;
    const int wrow = warp * 32;

    const float* Qg = Q + ((size_t)bh * S_ + qb * 128) * HD;
    const float* Kg = K + (size_t)bh * S_ * HD;
    const float* Vg = V + (size_t)bh * S_ * HD;

    const uint32_t ks_smem = (uint32_t)__cvta_generic_to_shared(Ks);
    const uint32_t vs_smem = (uint32_t)__cvta_generic_to_shared(Vs);

    const int lr = tid >> 4;
    const int lc = (tid & 15) << 2;

    auto issue_tile = [&](int t, int b) {
        const float* kg = Kg + (size_t)t * 64 * HD;
        const float* vg = Vg + (size_t)t * 64 * HD;
#pragma unroll
        for (int rr = 0; rr < 8; rr++) {
            const int r = lr + rr * 8;
            cp_async16(ks_smem + (b * KBUF + r * KLD + lc) * 4, kg + r * HD + lc);
            cp_async16(vs_smem + (b * VBUF + r * VLD + lc) * 4, vg + r * HD + lc);
        }
        cp_commit();
    };

    issue_tile(0, 0);

    for (int i = tid; i < 2048; i += 128) {
        const int r = i >> 4, c4 = (i & 15) << 2;
        float4 v = ((const float4*)Qg)[i];
        Ps[r * PLD + c4 + 0] = f2tf(v.x * 0.125f);
        Ps[r * PLD + c4 + 1] = f2tf(v.y * 0.125f);
        Ps[r * PLD + c4 + 2] = f2tf(v.z * 0.125f);
        Ps[r * PLD + c4 + 3] = f2tf(v.w * 0.125f);
    }
    __syncthreads();

    uint32_t qf[2][8][4];
#pragma unroll
    for (int mi = 0; mi < 2; mi++) {
        const int r0 = wrow + mi * 16 + g;
#pragma unroll
        for (int ks = 0; ks < 8; ks++) {
            qf[mi][ks][0] = Ps[r0 * PLD + ks * 8 + c];
            qf[mi][ks][1] = Ps[(r0 + 8) * PLD + ks * 8 + c];
            qf[mi][ks][2] = Ps[r0 * PLD + ks * 8 + c + 4];
            qf[mi][ks][3] = Ps[(r0 + 8) * PLD + ks * 8 + c + 4];
        }
    }

    float oacc[2][8][4];
#pragma unroll
    for (int mi = 0; mi < 2; mi++)
#pragma unroll
        for (int nt = 0; nt < 8; nt++)
#pragma unroll
            for (int k = 0; k < 4; k++) oacc[mi][nt][k] = 0.0f;
    float mI[2][2] = {{-3.0e38f, -3.0e38f}, {-3.0e38f, -3.0e38f}};
    float lI[2][2] = {{0.0f, 0.0f}, {0.0f, 0.0f}};

    const int jmax = 2 * qb + 1;
    int buf = 0;
    for (int j = 0; j <= jmax; j++) {
        cp_wait0();
        __syncthreads();
        if (j < jmax) issue_tile(j + 1, buf ^ 1);

        const uint32_t* Kb = Ks + buf * KBUF;
        const uint32_t* Vb = Vs + buf * VBUF;

        int ntlim = 8;
        const bool diag = (j >= 2 * qb);
        if (diag) {
            const int t = j - 2 * qb;
            const int lim = ((wrow + 31 - 64 * t) >> 3) + 1;
            ntlim = lim < 0 ? 0 : (lim > 8 ? 8 : lim);
        }

        if (ntlim > 0) {
            float sacc[2][8][4];
#pragma unroll
            for (int mi = 0; mi < 2; mi++)
#pragma unroll
                for (int nt = 0; nt < 8; nt++)
#pragma unroll
                    for (int k = 0; k < 4; k++) sacc[mi][nt][k] = 0.0f;

            if (ntlim == 8) {
                // full tile: ks-outer / nt-inner, fully unrolled ->
                // 16 independent accumulator chains between dependent MMAs
#pragma unroll
                for (int ks = 0; ks < 8; ks++) {
#pragma unroll
                    for (int nt = 0; nt < 8; nt++) {
                        uint32_t bf[2];
                        bf[0] = Kb[(nt * 8 + g) * KLD + ks * 8 + c];
                        bf[1] = Kb[(nt * 8 + g) * KLD + ks * 8 + c + 4];
                        mma_tf32(sacc[0][nt], qf[0][ks], bf);
                        mma_tf32(sacc[1][nt], qf[1][ks], bf);
                    }
                }
            } else {
                // diagonal tile: runtime nt bound (same ks-ascending order)
                for (int nt = 0; nt < ntlim; nt++) {
#pragma unroll
                    for (int ks = 0; ks < 8; ks++) {
                        uint32_t bf[2];
                        bf[0] = Kb[(nt * 8 + g) * KLD + ks * 8 + c];
                        bf[1] = Kb[(nt * 8 + g) * KLD + ks * 8 + c + 4];
                        mma_tf32(sacc[0][nt], qf[0][ks], bf);
                        mma_tf32(sacc[1][nt], qf[1][ks], bf);
                    }
                }
            }

            if (diag) {
#pragma unroll
                for (int mi = 0; mi < 2; mi++) {
                    const int r0 = qb * 128 + wrow + mi * 16 + g;
                    const int r1 = r0 + 8;
                    for (int nt = 0; nt < ntlim; nt++) {
                        const int col = j * 64 + nt * 8 + 2 * c;
                        if (col     > r0) sacc[mi][nt][0] = -3.0e38f;
                        if (col + 1 > r0) sacc[mi][nt][1] = -3.0e38f;
                        if (col     > r1) sacc[mi][nt][2] = -3.0e38f;
                        if (col + 1 > r1) sacc[mi][nt][3] = -3.0e38f;
                    }
                }
            }

            __syncwarp();
#pragma unroll
            for (int mi = 0; mi < 2; mi++) {
                float rmax0 = -3.0e38f, rmax1 = -3.0e38f;
                for (int nt = 0; nt < ntlim; nt++) {
                    rmax0 = fmaxf(rmax0, fmaxf(sacc[mi][nt][0], sacc[mi][nt][1]));
                    rmax1 = fmaxf(rmax1, fmaxf(sacc[mi][nt][2], sacc[mi][nt][3]));
                }
#pragma unroll
                for (int off = 1; off < 4; off <<= 1) {
                    rmax0 = fmaxf(rmax0, __shfl_xor_sync(0xffffffffu, rmax0, off));
                    rmax1 = fmaxf(rmax1, __shfl_xor_sync(0xffffffffu, rmax1, off));
                }

                const float mn0 = fmaxf(mI[mi][0], rmax0);
                const float mn1 = fmaxf(mI[mi][1], rmax1);
                const float al0 = __expf(mI[mi][0] - mn0);
                const float al1 = __expf(mI[mi][1] - mn1);

                const int r0 = wrow + mi * 16 + g;
                float rsum0 = 0.0f, rsum1 = 0.0f;
                for (int nt = 0; nt < ntlim; nt++) {
                    const float p0 = __expf(sacc[mi][nt][0] - mn0);
                    const float p1 = __expf(sacc[mi][nt][1] - mn0);
                    const float p2 = __expf(sacc[mi][nt][2] - mn1);
                    const float p3 = __expf(sacc[mi][nt][3] - mn1);
                    rsum0 += p0 + p1;
                    rsum1 += p2 + p3;
                    *(uint2*)&Ps[r0 * PLD + nt * 8 + 2 * c] =
                        make_uint2(f2tf(p0), f2tf(p1));
                    *(uint2*)&Ps[(r0 + 8) * PLD + nt * 8 + 2 * c] =
                        make_uint2(f2tf(p2), f2tf(p3));
                }
#pragma unroll
                for (int off = 1; off < 4; off <<= 1) {
                    rsum0 += __shfl_xor_sync(0xffffffffu, rsum0, off);
                    rsum1 += __shfl_xor_sync(0xffffffffu, rsum1, off);
                }
                lI[mi][0] = lI[mi][0] * al0 + rsum0;
                lI[mi][1] = lI[mi][1] * al1 + rsum1;
                mI[mi][0] = mn0;
                mI[mi][1] = mn1;
#pragma unroll
                for (int nt = 0; nt < 8; nt++) {
                    oacc[mi][nt][0] *= al0;
                    oacc[mi][nt][1] *= al0;
                    oacc[mi][nt][2] *= al1;
                    oacc[mi][nt][3] *= al1;
                }
            }
            __syncwarp();

            for (int ks = 0; ks < ntlim; ks++) {
                uint32_t af0[4], af1[4];
                const int pr0 = wrow + g;
                af0[0] = Ps[pr0 * PLD + ks * 8 + c];
                af0[1] = Ps[(pr0 + 8) * PLD + ks * 8 + c];
                af0[2] = Ps[pr0 * PLD + ks * 8 + c + 4];
                af0[3] = Ps[(pr0 + 8) * PLD + ks * 8 + c + 4];
                af1[0] = Ps[(pr0 + 16) * PLD + ks * 8 + c];
                af1[1] = Ps[(pr0 + 24) * PLD + ks * 8 + c];
                af1[2] = Ps[(pr0 + 16) * PLD + ks * 8 + c + 4];
                af1[3] = Ps[(pr0 + 24) * PLD + ks * 8 + c + 4];
#pragma unroll
                for (int nt = 0; nt < 8; nt++) {
                    uint32_t bf[2];
                    bf[0] = Vb[(ks * 8 + c)     * VLD + nt * 8 + g];
                    bf[1] = Vb[(ks * 8 + c + 4) * VLD + nt * 8 + g];
                    mma_tf32(oacc[0][nt], af0, bf);
                    mma_tf32(oacc[1][nt], af1, bf);
                }
            }
        }
        buf ^= 1;
    }

    const int b = bh >> 4, h = bh & 15;
#pragma unroll
    for (int mi = 0; mi < 2; mi++) {
        const int r0 = qb * 128 + wrow + mi * 16 + g;
        const int r1 = r0 + 8;
        const float inv0 = 1.0f / lI[mi][0];
        const float inv1 = 1.0f / lI[mi][1];
#pragma unroll
        for (int nt = 0; nt < 8; nt++) {
            const int col = h * 64 + nt * 8 + 2 * c;
            *(float2*)&ctx[(size_t)(b * S_ + r0) * DIM + col] =
                make_float2(tfr(oacc[mi][nt][0] * inv0), tfr(oacc[mi][nt][1] * inv0));
            *(float2*)&ctx[(size_t)(b * S_ + r1) * DIM + col] =
                make_float2(tfr(oacc[mi][nt][2] * inv1), tfr(oacc[mi][nt][3] * inv1));
        }
    }
}

// ---------------------------------------------------------------------------
extern "C" void kernel_launch(void* const* d_in, const int* in_sizes, int n_in,
                              void* d_out, int out_size)
{
    const float* x     = (const float*)d_in[0];
    const float* theta = (const float*)d_in[2];
    const float* Wq    = (const float*)d_in[3];
    const float* bq    = (const float*)d_in[4];
    const float* Wk    = (const float*)d_in[5];
    const float* bk    = (const float*)d_in[6];
    const float* Wv    = (const float*)d_in[7];
    const float* bv    = (const float*)d_in[8];
    const float* Wo    = (const float*)d_in[9];
    const float* bo    = (const float*)d_in[10];
    float* out = (float*)d_out;

    float *Qb, *Kb, *Vb, *Cb, *Xr, *Wr;
    cudaGetSymbolAddress((void**)&Qb, g_Q);
    cudaGetSymbolAddress((void**)&Kb, g_K);
    cudaGetSymbolAddress((void**)&Vb, g_V);
    cudaGetSymbolAddress((void**)&Cb, g_C);
    cudaGetSymbolAddress((void**)&Xr, g_Xr);
    cudaGetSymbolAddress((void**)&Wr, g_Wr);

    round_tf32_kernel<<<(X4 + 4 * W4) / 256, 256>>>(x, Wq, Wk, Wv, Wo, Xr, Wr);

    gemm_tf32_kernel<1><<<dim3(3 * DIM / 128, MROWS / 128), 128>>>(
        Xr, Wr, bq, bk, bv, Qb, Kb, Vb);

    rope_kernel<<<(B_ * NH * S_ * 32) / 256, 256>>>(Qb, Kb, theta);

    const int flashSmem = FLASH_SMEM_WORDS * (int)sizeof(uint32_t);  // 106.5 KB
    cudaFuncSetAttribute(flash_tf32_kernel,
                         cudaFuncAttributeMaxDynamicSharedMemorySize, flashSmem);
    flash_tf32_kernel<<<16 * 32, 128, flashSmem>>>(Qb, Kb, Vb, Cb);

    gemm_tf32_kernel<0><<<dim3(DIM / 128, MROWS / 128), 128>>>(
        Cb, Wr + (size_t)3 * DIM * DIM, bo, bo, bo, out, out, out);
}

// round 15
// speedup vs baseline: 1.0019x; 1.0019x over previous
#include <cuda_runtime.h>
#include <math.h>
#include <stdint.h>

#define DIM   1024
#define NH    16
#define HD    64
#define B_    2
#define S_    2048
#define MROWS (B_ * S_)   // 4096

// Scratch (allocation-free rule: __device__ globals)
__device__ float g_Q[B_ * NH * S_ * HD];   // [B,H,S,hd]
__device__ float g_K[B_ * NH * S_ * HD];
__device__ float g_V[B_ * NH * S_ * HD];
__device__ float g_C[MROWS * DIM];         // attention context (tf32-rounded)
__device__ float g_Xr[MROWS * DIM];        // x, tf32-RNA-rounded
__device__ float g_Wr[4 * DIM * DIM];      // Wq|Wk|Wv|Wo, tf32-RNA-rounded

// ---------------------------------------------------------------------------
// TF32 / async helpers
// ---------------------------------------------------------------------------
__device__ __forceinline__ uint32_t f2tf(float f) {
    uint32_t r;
    asm("cvt.rna.tf32.f32 %0, %1;" : "=r"(r) : "f"(f));
    return r;
}
__device__ __forceinline__ float tfr(float f) { return __uint_as_float(f2tf(f)); }

__device__ __forceinline__ void mma_tf32(float* d, const uint32_t* a, const uint32_t* b) {
    asm volatile(
        "mma.sync.aligned.m16n8k8.row.col.f32.tf32.tf32.f32 "
        "{%0,%1,%2,%3}, {%4,%5,%6,%7}, {%8,%9}, {%0,%1,%2,%3};"
        : "+f"(d[0]), "+f"(d[1]), "+f"(d[2]), "+f"(d[3])
        : "r"(a[0]), "r"(a[1]), "r"(a[2]), "r"(a[3]),
          "r"(b[0]), "r"(b[1]));
}

__device__ __forceinline__ void cp_async16(uint32_t smem_byte_addr, const void* gptr) {
    asm volatile("cp.async.cg.shared.global [%0], [%1], 16;"
                 :: "r"(smem_byte_addr), "l"(gptr));
}
__device__ __forceinline__ void cp_commit() { asm volatile("cp.async.commit_group;"); }
__device__ __forceinline__ void cp_wait0()  { asm volatile("cp.async.wait_group 0;"); }

// ---------------------------------------------------------------------------
// Pre-round x and the four weight matrices to tf32-RNA.
// ---------------------------------------------------------------------------
#define X4 (MROWS * DIM / 4)   // 1048576
#define W4 (DIM * DIM / 4)     // 262144

__global__ void round_tf32_kernel(
    const float* __restrict__ x,
    const float* __restrict__ wq, const float* __restrict__ wk,
    const float* __restrict__ wv, const float* __restrict__ wo,
    float* __restrict__ xr, float* __restrict__ wr)
{
    const int gid = blockIdx.x * blockDim.x + threadIdx.x;
    const float4* src;
    float4* dst;
    int idx;
    if (gid < X4) {
        src = (const float4*)x;  dst = (float4*)xr;  idx = gid;
    } else {
        const int t = gid - X4;
        const int w = t >> 18;          // / W4
        idx = t & (W4 - 1);
        src = (const float4*)(w == 0 ? wq : w == 1 ? wk : w == 2 ? wv : wo);
        dst = (float4*)(wr + (size_t)w * DIM * DIM);
    }
    float4 v = src[idx];
    v.x = tfr(v.x); v.y = tfr(v.y); v.z = tfr(v.z); v.w = tfr(v.w);
    dst[idx] = v;
}

// ---------------------------------------------------------------------------
// TF32 GEMM v2: 128 threads, 4 warps, warp tile 64x64 (2x2 warp grid).
// Block 128x128x16, cp.async double-buffered, 1 barrier/tile.
// QKV=1: fused N=3072 (per-CTA weight select), scatter to [B,H,S,hd], tfr out.
// QKV=0: N=1024, row-major out + bias.
// ---------------------------------------------------------------------------
#define LDA 20
#define LDB 136

template<int QKV>
__global__ __launch_bounds__(128, 2) void gemm_tf32_kernel(
    const float* __restrict__ A, const float* __restrict__ Wall,
    const float* __restrict__ b0, const float* __restrict__ b1,
    const float* __restrict__ b2,
    float* __restrict__ O0, float* __restrict__ O1, float* __restrict__ O2)
{
    __shared__ uint32_t As[2][128 * LDA];
    __shared__ uint32_t Bs[2][16 * LDB];

    const int tid  = threadIdx.x;
    const int lane = tid & 31;
    const int warp = tid >> 5;
    const int bm  = blockIdx.y * 128;
    const int bnG = blockIdx.x * 128;
    const int wsel = bnG >> 10;
    const int bn   = bnG & 1023;
    const int wm = (warp & 1) << 6;      // 0 / 64
    const int wn = (warp >> 1) << 6;     // 0 / 64

    const float* W    = Wall + (size_t)wsel * DIM * DIM;
    const float* bias = QKV ? (wsel == 0 ? b0 : (wsel == 1 ? b1 : b2)) : b0;
    float* Osel = QKV ? (wsel == 0 ? O0 : (wsel == 1 ? O1 : O2)) : O0;

    const int ar  = tid >> 2;            // 0..31 (+32,+64,+96)
    const int akc = (tid & 3) << 2;
    const int bk  = tid >> 5;            // 0..3 (+4,+8,+12)
    const int bnc = (tid & 31) << 2;

    const float* Ap = A + (size_t)(bm + ar) * DIM + akc;
    const float* Bp = W + (size_t)bk * DIM + bn + bnc;

    const uint32_t as_b = (uint32_t)__cvta_generic_to_shared(As);
    const uint32_t bs_b = (uint32_t)__cvta_generic_to_shared(Bs);

    auto issue = [&](int kt, int bf) {
        const float* a = Ap + kt * 16;
#pragma unroll
        for (int rr = 0; rr < 4; rr++)
            cp_async16(as_b + (bf * 128 * LDA + (ar + rr * 32) * LDA + akc) * 4,
                       a + (size_t)(rr * 32) * DIM);
        const float* b = Bp + (size_t)kt * 16 * DIM;
#pragma unroll
        for (int rr = 0; rr < 4; rr++)
            cp_async16(bs_b + (bf * 16 * LDB + (bk + rr * 4) * LDB + bnc) * 4,
                       b + (size_t)(rr * 4) * DIM);
        cp_commit();
    };

    float acc[32][4];
#pragma unroll
    for (int i = 0; i < 32; i++)
#pragma unroll
        for (int j = 0; j < 4; j++) acc[i][j] = 0.0f;

    issue(0, 0);

    const int NT = DIM / 16;
#pragma unroll 1
    for (int kt = 0; kt < NT; kt++) {
        cp_wait0();
        __syncthreads();
        if (kt + 1 < NT) issue(kt + 1, (kt + 1) & 1);
        const int cur = kt & 1;

#pragma unroll
        for (int ks = 0; ks < 2; ks++) {
            uint32_t af[4][4], bf[8][2];
#pragma unroll
            for (int mi = 0; mi < 4; mi++) {
                const int r = wm + mi * 16 + (lane >> 2);
                const int c = ks * 8 + (lane & 3);
                af[mi][0] = As[cur][r * LDA + c];
                af[mi][1] = As[cur][(r + 8) * LDA + c];
                af[mi][2] = As[cur][r * LDA + c + 4];
                af[mi][3] = As[cur][(r + 8) * LDA + c + 4];
            }
#pragma unroll
            for (int ni = 0; ni < 8; ni++) {
                const int n = wn + ni * 8 + (lane >> 2);
                const int k = ks * 8 + (lane & 3);
                bf[ni][0] = Bs[cur][k * LDB + n];
                bf[ni][1] = Bs[cur][(k + 4) * LDB + n];
            }
#pragma unroll
            for (int mi = 0; mi < 4; mi++)
#pragma unroll
                for (int ni = 0; ni < 8; ni++)
                    mma_tf32(acc[mi * 8 + ni], af[mi], bf[ni]);
        }
    }

#pragma unroll
    for (int mi = 0; mi < 4; mi++) {
        const int r0 = bm + wm + mi * 16 + (lane >> 2);
        const int r1 = r0 + 8;
#pragma unroll
        for (int ni = 0; ni < 8; ni++) {
            const int c0 = bn + wn + ni * 8 + ((lane & 3) << 1);
            const float* a = acc[mi * 8 + ni];
            const float bi0 = bias[c0], bi1 = bias[c0 + 1];
            if (QKV == 0) {
                *(float2*)&Osel[(size_t)r0 * DIM + c0] = make_float2(a[0] + bi0, a[1] + bi1);
                *(float2*)&Osel[(size_t)r1 * DIM + c0] = make_float2(a[2] + bi0, a[3] + bi1);
            } else {
                const int h = c0 >> 6, d = c0 & 63;
                const int b0r = r0 >> 11, s0 = r0 & (S_ - 1);
                const int b1r = r1 >> 11, s1 = r1 & (S_ - 1);
                *(float2*)&Osel[(((size_t)(b0r * NH + h)) * S_ + s0) * HD + d] =
                    make_float2(tfr(a[0] + bi0), tfr(a[1] + bi1));
                *(float2*)&Osel[(((size_t)(b1r * NH + h)) * S_ + s1) * HD + d] =
                    make_float2(tfr(a[2] + bi0), tfr(a[3] + bi1));
            }
        }
    }
}

// ---------------------------------------------------------------------------
// RoPE (in-place on Q and K), tf32-RNA-rounded outputs.
// ---------------------------------------------------------------------------
__global__ void rope_kernel(float* __restrict__ Q, float* __restrict__ K,
                            const float* __restrict__ theta)
{
    const int gid  = blockIdx.x * blockDim.x + threadIdx.x;
    const int warp = gid >> 5;
    const int lane = gid & 31;
    const int s = warp & (S_ - 1);

    const float th = theta[lane];
    float sn, cs;
    sincosf((float)s * th, &sn, &cs);

    float* q = Q + (size_t)warp * HD;
    float x1 = q[2 * lane], x2 = q[2 * lane + 1];
    __syncwarp();
    q[lane]      = tfr(x1 * cs - x2 * sn);
    q[lane + 32] = tfr(x1 * sn + x2 * cs);

    float* k = K + (size_t)warp * HD;
    float y1 = k[2 * lane], y2 = k[2 * lane + 1];
    __syncwarp();
    k[lane]      = tfr(y1 * cs - y2 * sn);
    k[lane + 32] = tfr(y1 * sn + y2 * cs);
}

// ---------------------------------------------------------------------------
// TF32 flash attention v6: as v5 (4 warps, 32 q-rows/warp, register Q,
// cp.async double buffer, diag skip) + QK^T loop interchange on full tiles:
// ks-outer / nt-inner fully unrolled -> 16 independent MMA chains (was 2),
// removing the dependent-MMA stall that capped tensor pipe at ~38%.
// Per-accumulator k-order unchanged (ks ascending) -> bit-identical output.
// ---------------------------------------------------------------------------
#define KLD 68
#define VLD 72
#define PLD 68
#define KBUF (64 * KLD)
#define VBUF (64 * VLD)
#define FLASH_SMEM_WORDS (2*KBUF + 2*VBUF + 128*PLD)   // 106.5 KB

__global__ __launch_bounds__(128, 2) void flash_tf32_kernel(
    const float* __restrict__ Q, const float* __restrict__ K,
    const float* __restrict__ V, float* __restrict__ ctx)
{
    extern __shared__ uint32_t sm[];
    uint32_t* Ks = sm;
    uint32_t* Vs = Ks + 2 * KBUF;
    uint32_t* Ps = Vs + 2 * VBUF;

    const int bid  = blockIdx.x;
    const int qb   = 15 - (bid >> 5);
    const int bh   = bid & 31;
    const int tid  = threadIdx.x;
    const int lane = tid & 31;
    const int warp = tid >> 5;
    const int g = lane >> 2;
    const int c = lane & 3;
    const int wrow = warp * 32;

    const float* Qg = Q + ((size_t)bh * S_ + qb * 128) * HD;
    const float* Kg = K + (size_t)bh * S_ * HD;
    const float* Vg = V + (size_t)bh * S_ * HD;

    const uint32_t ks_smem = (uint32_t)__cvta_generic_to_shared(Ks);
    const uint32_t vs_smem = (uint32_t)__cvta_generic_to_shared(Vs);

    const int lr = tid >> 4;
    const int lc = (tid & 15) << 2;

    auto issue_tile = [&](int t, int b) {
        const float* kg = Kg + (size_t)t * 64 * HD;
        const float* vg = Vg + (size_t)t * 64 * HD;
#pragma unroll
        for (int rr = 0; rr < 8; rr++) {
            const int r = lr + rr * 8;
            cp_async16(ks_smem + (b * KBUF + r * KLD + lc) * 4, kg + r * HD + lc);
            cp_async16(vs_smem + (b * VBUF + r * VLD + lc) * 4, vg + r * HD + lc);
        }
        cp_commit();
    };

    issue_tile(0, 0);

    for (int i = tid; i < 2048; i += 128) {
        const int r = i >> 4, c4 = (i & 15) << 2;
        float4 v = ((const float4*)Qg)[i];
        Ps[r * PLD + c4 + 0] = f2tf(v.x * 0.125f);
        Ps[r * PLD + c4 + 1] = f2tf(v.y * 0.125f);
        Ps[r * PLD + c4 + 2] = f2tf(v.z * 0.125f);
        Ps[r * PLD + c4 + 3] = f2tf(v.w * 0.125f);
    }
    __syncthreads();

    uint32_t qf[2][8][4];
#pragma unroll
    for (int mi = 0; mi < 2; mi++) {
        const int r0 = wrow + mi * 16 + g;
#pragma unroll
        for (int ks = 0; ks < 8; ks++) {
            qf[mi][ks][0] = Ps[r0 * PLD + ks * 8 + c];
            qf[mi][ks][1] = Ps[(r0 + 8) * PLD + ks * 8 + c];
            qf[mi][ks][2] = Ps[r0 * PLD + ks * 8 + c + 4];
            qf[mi][ks][3] = Ps[(r0 + 8) * PLD + ks * 8 + c + 4];
        }
    }

    float oacc[2][8][4];
#pragma unroll
    for (int mi = 0; mi < 2; mi++)
#pragma unroll
        for (int nt = 0; nt < 8; nt++)
#pragma unroll
            for (int k = 0; k < 4; k++) oacc[mi][nt][k] = 0.0f;
    float mI[2][2] = {{-3.0e38f, -3.0e38f}, {-3.0e38f, -3.0e38f}};
    float lI[2][2] = {{0.0f, 0.0f}, {0.0f, 0.0f}};

    const int jmax = 2 * qb + 1;
    int buf = 0;
    for (int j = 0; j <= jmax; j++) {
        cp_wait0();
        __syncthreads();
        if (j < jmax) issue_tile(j + 1, buf ^ 1);

        const uint32_t* Kb = Ks + buf * KBUF;
        const uint32_t* Vb = Vs + buf * VBUF;

        int ntlim = 8;
        const bool diag = (j >= 2 * qb);
        if (diag) {
            const int t = j - 2 * qb;
            const int lim = ((wrow + 31 - 64 * t) >> 3) + 1;
            ntlim = lim < 0 ? 0 : (lim > 8 ? 8 : lim);
        }

        if (ntlim > 0) {
            float sacc[2][8][4];
#pragma unroll
            for (int mi = 0; mi < 2; mi++)
#pragma unroll
                for (int nt = 0; nt < 8; nt++)
#pragma unroll
                    for (int k = 0; k < 4; k++) sacc[mi][nt][k] = 0.0f;

            if (ntlim == 8) {
                // full tile: ks-outer / nt-inner, fully unrolled ->
                // 16 independent accumulator chains between dependent MMAs
#pragma unroll
                for (int ks = 0; ks < 8; ks++) {
#pragma unroll
                    for (int nt = 0; nt < 8; nt++) {
                        uint32_t bf[2];
                        bf[0] = Kb[(nt * 8 + g) * KLD + ks * 8 + c];
                        bf[1] = Kb[(nt * 8 + g) * KLD + ks * 8 + c + 4];
                        mma_tf32(sacc[0][nt], qf[0][ks], bf);
                        mma_tf32(sacc[1][nt], qf[1][ks], bf);
                    }
                }
            } else {
                // diagonal tile: runtime nt bound (same ks-ascending order)
                for (int nt = 0; nt < ntlim; nt++) {
#pragma unroll
                    for (int ks = 0; ks < 8; ks++) {
                        uint32_t bf[2];
                        bf[0] = Kb[(nt * 8 + g) * KLD + ks * 8 + c];
                        bf[1] = Kb[(nt * 8 + g) * KLD + ks * 8 + c + 4];
                        mma_tf32(sacc[0][nt], qf[0][ks], bf);
                        mma_tf32(sacc[1][nt], qf[1][ks], bf);
                    }
                }
            }

            if (diag) {
#pragma unroll
                for (int mi = 0; mi < 2; mi++) {
                    const int r0 = qb * 128 + wrow + mi * 16 + g;
                    const int r1 = r0 + 8;
                    for (int nt = 0; nt < ntlim; nt++) {
                        const int col = j * 64 + nt * 8 + 2 * c;
                        if (col     > r0) sacc[mi][nt][0] = -3.0e38f;
                        if (col + 1 > r0) sacc[mi][nt][1] = -3.0e38f;
                        if (col     > r1) sacc[mi][nt][2] = -3.0e38f;
                        if (col + 1 > r1) sacc[mi][nt][3] = -3.0e38f;
                    }
                }
            }

            __syncwarp();
#pragma unroll
            for (int mi = 0; mi < 2; mi++) {
                float rmax0 = -3.0e38f, rmax1 = -3.0e38f;
                for (int nt = 0; nt < ntlim; nt++) {
                    rmax0 = fmaxf(rmax0, fmaxf(sacc[mi][nt][0], sacc[mi][nt][1]));
                    rmax1 = fmaxf(rmax1, fmaxf(sacc[mi][nt][2], sacc[mi][nt][3]));
                }
#pragma unroll
                for (int off = 1; off < 4; off <<= 1) {
                    rmax0 = fmaxf(rmax0, __shfl_xor_sync(0xffffffffu, rmax0, off));
                    rmax1 = fmaxf(rmax1, __shfl_xor_sync(0xffffffffu, rmax1, off));
                }

                const float mn0 = fmaxf(mI[mi][0], rmax0);
                const float mn1 = fmaxf(mI[mi][1], rmax1);
                const float al0 = __expf(mI[mi][0] - mn0);
                const float al1 = __expf(mI[mi][1] - mn1);

                const int r0 = wrow + mi * 16 + g;
                float rsum0 = 0.0f, rsum1 = 0.0f;
                for (int nt = 0; nt < ntlim; nt++) {
                    const float p0 = __expf(sacc[mi][nt][0] - mn0);
                    const float p1 = __expf(sacc[mi][nt][1] - mn0);
                    const float p2 = __expf(sacc[mi][nt][2] - mn1);
                    const float p3 = __expf(sacc[mi][nt][3] - mn1);
                    rsum0 += p0 + p1;
                    rsum1 += p2 + p3;
                    *(uint2*)&Ps[r0 * PLD + nt * 8 + 2 * c] =
                        make_uint2(f2tf(p0), f2tf(p1));
                    *(uint2*)&Ps[(r0 + 8) * PLD + nt * 8 + 2 * c] =
                        make_uint2(f2tf(p2), f2tf(p3));
                }
#pragma unroll
                for (int off = 1; off < 4; off <<= 1) {
                    rsum0 += __shfl_xor_sync(0xffffffffu, rsum0, off);
                    rsum1 += __shfl_xor_sync(0xffffffffu, rsum1, off);
                }
                lI[mi][0] = lI[mi][0] * al0 + rsum0;
                lI[mi][1] = lI[mi][1] * al1 + rsum1;
                mI[mi][0] = mn0;
                mI[mi][1] = mn1;
#pragma unroll
                for (int nt = 0; nt < 8; nt++) {
                    oacc[mi][nt][0] *= al0;
                    oacc[mi][nt][1] *= al0;
                    oacc[mi][nt][2] *= al1;
                    oacc[mi][nt][3] *= al1;
                }
            }
            __syncwarp();

            for (int ks = 0; ks < ntlim; ks++) {
                uint32_t af0[4], af1[4];
                const int pr0 = wrow + g;
                af0[0] = Ps[pr0 * PLD + ks * 8 + c];
                af0[1] = Ps[(pr0 + 8) * PLD + ks * 8 + c];
                af0[2] = Ps[pr0 * PLD + ks * 8 + c + 4];
                af0[3] = Ps[(pr0 + 8) * PLD + ks * 8 + c + 4];
                af1[0] = Ps[(pr0 + 16) * PLD + ks * 8 + c];
                af1[1] = Ps[(pr0 + 24) * PLD + ks * 8 + c];
                af1[2] = Ps[(pr0 + 16) * PLD + ks * 8 + c + 4];
                af1[3] = Ps[(pr0 + 24) * PLD + ks * 8 + c + 4];
#pragma unroll
                for (int nt = 0; nt < 8; nt++) {
                    uint32_t bf[2];
                    bf[0] = Vb[(ks * 8 + c)     * VLD + nt * 8 + g];
                    bf[1] = Vb[(ks * 8 + c + 4) * VLD + nt * 8 + g];
                    mma_tf32(oacc[0][nt], af0, bf);
                    mma_tf32(oacc[1][nt], af1, bf);
                }
            }
        }
        buf ^= 1;
    }

    const int b = bh >> 4, h = bh & 15;
#pragma unroll
    for (int mi = 0; mi < 2; mi++) {
        const int r0 = qb * 128 + wrow + mi * 16 + g;
        const int r1 = r0 + 8;
        const float inv0 = 1.0f / lI[mi][0];
        const float inv1 = 1.0f / lI[mi][1];
#pragma unroll
        for (int nt = 0; nt < 8; nt++) {
            const int col = h * 64 + nt * 8 + 2 * c;
            *(float2*)&ctx[(size_t)(b * S_ + r0) * DIM + col] =
                make_float2(tfr(oacc[mi][nt][0] * inv0), tfr(oacc[mi][nt][1] * inv0));
            *(float2*)&ctx[(size_t)(b * S_ + r1) * DIM + col] =
                make_float2(tfr(oacc[mi][nt][2] * inv1), tfr(oacc[mi][nt][3] * inv1));
        }
    }
}

// ---------------------------------------------------------------------------
extern "C" void kernel_launch(void* const* d_in, const int* in_sizes, int n_in,
                              void* d_out, int out_size)
{
    const float* x     = (const float*)d_in[0];
    const float* theta = (const float*)d_in[2];
    const float* Wq    = (const float*)d_in[3];
    const float* bq    = (const float*)d_in[4];
    const float* Wk    = (const float*)d_in[5];
    const float* bk    = (const float*)d_in[6];
    const float* Wv    = (const float*)d_in[7];
    const float* bv    = (const float*)d_in[8];
    const float* Wo    = (const float*)d_in[9];
    const float* bo    = (const float*)d_in[10];
    float* out = (float*)d_out;

    float *Qb, *Kb, *Vb, *Cb, *Xr, *Wr;
    cudaGetSymbolAddress((void**)&Qb, g_Q);
    cudaGetSymbolAddress((void**)&Kb, g_K);
    cudaGetSymbolAddress((void**)&Vb, g_V);
    cudaGetSymbolAddress((void**)&Cb, g_C);
    cudaGetSymbolAddress((void**)&Xr, g_Xr);
    cudaGetSymbolAddress((void**)&Wr, g_Wr);

    round_tf32_kernel<<<(X4 + 4 * W4) / 256, 256>>>(x, Wq, Wk, Wv, Wo, Xr, Wr);

    gemm_tf32_kernel<1><<<dim3(3 * DIM / 128, MROWS / 128), 128>>>(
        Xr, Wr, bq, bk, bv, Qb, Kb, Vb);

    rope_kernel<<<(B_ * NH * S_ * 32) / 256, 256>>>(Qb, Kb, theta);

    const int flashSmem = FLASH_SMEM_WORDS * (int)sizeof(uint32_t);  // 106.5 KB
    cudaFuncSetAttribute(flash_tf32_kernel,
                         cudaFuncAttributeMaxDynamicSharedMemorySize, flashSmem);
    flash_tf32_kernel<<<16 * 32, 128, flashSmem>>>(Qb, Kb, Vb, Cb);

    gemm_tf32_kernel<0><<<dim3(DIM / 128, MROWS / 128), 128>>>(
        Cb, Wr + (size_t)3 * DIM * DIM, bo, bo, bo, out, out, out);
}